// round 8
// baseline (speedup 1.0000x reference)
#include <cuda_runtime.h>

// Problem constants (fixed by the reference):
// B=16, W=256, S=512, F=768, L=4, E=256, V=50000
#define BB 16
#define WW 256
#define SS 512
#define NW (WW - 1)
#define NTOT (BB * WW)      // 4096 word tasks
#define NCTA 456            // 152 SMs * 3 resident CTAs (persistent)

// float4 strides inside layers[L, B, S, F/4=192]
#define LSTRIDE (BB * SS * 192)   // 1,572,864
#define BSTRIDE (SS * 192)        //    98,304

// Streaming load: non-coherent, 256B L2 fill granularity.
__device__ __forceinline__ float4 ldg_stream(const float4* p) {
    float4 v;
    asm("ld.global.nc.L2::256B.v4.f32 {%0,%1,%2,%3}, [%4];"
        : "=f"(v.x), "=f"(v.y), "=f"(v.z), "=f"(v.w)
        : "l"(p));
    return v;
}

// Generic (slow) path: arbitrary span. Only taken if the speculation
// (ss == 2w-1, len == 2) misses — never with this dataset. Reloads the
// softmax inputs itself to keep the hot loop's register count down.
__device__ __noinline__ float4 span_mix_generic(
    const float4* __restrict__ layers4,
    const float* __restrict__ layer_weights, const float* __restrict__ gamma,
    int b, int ss, int se, int t)
{
    float4 acc = make_float4(0.f, 0.f, 0.f, 0.f);
    const int len = se - ss;
    if (len <= 0) return acc;
    const float lw0 = __ldg(layer_weights + 0), lw1 = __ldg(layer_weights + 1);
    const float lw2 = __ldg(layer_weights + 2), lw3 = __ldg(layer_weights + 3);
    const float g   = __ldg(gamma);
    const float mx  = fmaxf(fmaxf(lw0, lw1), fmaxf(lw2, lw3));
    const float e0  = __expf(lw0 - mx), e1 = __expf(lw1 - mx);
    const float e2  = __expf(lw2 - mx), e3 = __expf(lw3 - mx);
    const float inv = 1.0f / (e0 + e1 + e2 + e3);
    const float w0 = e0 * inv, w1 = e1 * inv, w2 = e2 * inv, w3 = e3 * inv;
    for (int s = ss; s < se; s++) {
        const float4* p = layers4 + (size_t)b * BSTRIDE + (size_t)s * 192 + t;
        float4 v0 = p[0 * LSTRIDE];
        float4 v1 = p[1 * LSTRIDE];
        float4 v2 = p[2 * LSTRIDE];
        float4 v3 = p[3 * LSTRIDE];
        acc.x += w0*v0.x + w1*v1.x + w2*v2.x + w3*v3.x;
        acc.y += w0*v0.y + w1*v1.y + w2*v2.y + w3*v3.y;
        acc.z += w0*v0.z + w1*v1.z + w2*v2.z + w3*v3.z;
        acc.w += w0*v0.w + w1*v1.w + w2*v2.w + w3*v3.w;
    }
    const float sc = g / (float)len;
    acc.x *= sc; acc.y *= sc; acc.z *= sc; acc.w *= sc;
    return acc;
}

// Per-task in-flight register state (one pipeline stage).
struct Stage {
    float4 L0, L1, L2, L3, L4, L5, L6, L7;  // 8 speculative layer float4s
    float4 ev;                               // embedding float4 (threads 0..63)
    int bw, ss, se;
};

// Issue all loads for word-task `bw`. Layer-load addresses are SPECULATED
// (ss_g = 2w-1, a pure function of bw) so the whole burst has no memory
// dependency in front of it; the true span indices fly concurrently and are
// verified at consume time.
__device__ __forceinline__ void issue_stage(
    Stage& S, int bw, int t, bool do_emb,
    const int* __restrict__ word_indices,
    const int* __restrict__ span_starts,
    const int* __restrict__ span_ends,
    const float4* __restrict__ emb4,
    const float4* __restrict__ layers4)
{
    S.bw = bw;
    const int b = bw >> 8;
    const int w = bw & (WW - 1);
    const int idx = __ldg(word_indices + bw);      // small, L2-resident
    if (w > 0) {
        const int ssg = (w << 1) - 1;              // in [1,509]; +1 < S
        const float4* base = layers4 + (size_t)b * BSTRIDE + (size_t)ssg * 192 + t;
        S.L0 = ldg_stream(base + 0 * LSTRIDE      );
        S.L1 = ldg_stream(base + 0 * LSTRIDE + 192);
        S.L2 = ldg_stream(base + 1 * LSTRIDE      );
        S.L3 = ldg_stream(base + 1 * LSTRIDE + 192);
        S.L4 = ldg_stream(base + 2 * LSTRIDE      );
        S.L5 = ldg_stream(base + 2 * LSTRIDE + 192);
        S.L6 = ldg_stream(base + 3 * LSTRIDE      );
        S.L7 = ldg_stream(base + 3 * LSTRIDE + 192);
        const int si = b * NW + (w - 1);
        S.ss = __ldg(span_starts + si);
        S.se = __ldg(span_ends   + si);
    } else {
        S.ss = 0; S.se = 0;
    }
    if (do_emb) S.ev = ldg_stream(emb4 + (size_t)idx * 64 + t);
    else        S.ev = make_float4(0.f, 0.f, 0.f, 0.f);
}

// Verify speculation, combine, and store task `S`.
__device__ __forceinline__ void consume_stage(
    const Stage& S, int t, bool do_emb,
    float h0, float h1, float h2, float h3,
    const float4* __restrict__ layers4,
    const float* __restrict__ layer_weights, const float* __restrict__ gamma,
    float4* __restrict__ out4)
{
    const int w = S.bw & (WW - 1);
    float4 acc = make_float4(0.f, 0.f, 0.f, 0.f);
    if (w > 0) {
        const int ssg = (w << 1) - 1;
        if (S.ss == ssg && S.se == ssg + 2) {
            acc.x = h0*(S.L0.x+S.L1.x) + h1*(S.L2.x+S.L3.x) + h2*(S.L4.x+S.L5.x) + h3*(S.L6.x+S.L7.x);
            acc.y = h0*(S.L0.y+S.L1.y) + h1*(S.L2.y+S.L3.y) + h2*(S.L4.y+S.L5.y) + h3*(S.L6.y+S.L7.y);
            acc.z = h0*(S.L0.z+S.L1.z) + h1*(S.L2.z+S.L3.z) + h2*(S.L4.z+S.L5.z) + h3*(S.L6.z+S.L7.z);
            acc.w = h0*(S.L0.w+S.L1.w) + h1*(S.L2.w+S.L3.w) + h2*(S.L4.w+S.L5.w) + h3*(S.L6.w+S.L7.w);
        } else {
            acc = span_mix_generic(layers4, layer_weights, gamma,
                                   S.bw >> 8, S.ss, S.se, t);
        }
    }
    float4* __restrict__ o = out4 + (size_t)S.bw * 256;
    if (do_emb) __stcs(o + t, S.ev);
    __stcs(o + 64 + t, acc);
}

// Persistent double-buffered pipeline: 456 CTAs x 192 threads grid-stride over
// 4096 word tasks. Each iteration issues the NEXT task's dependency-free load
// burst before consuming the CURRENT one, so every warp keeps ~8 LDG.128s in
// flight continuously — no CTA churn, no serial load->compute gaps.
__global__ __launch_bounds__(192, 3)
void bert_lexer_pipe(
    const int* __restrict__ word_indices,   // [B, W]
    const int* __restrict__ span_starts,    // [B, W-1]
    const int* __restrict__ span_ends,      // [B, W-1]
    const float4* __restrict__ emb4,        // [V, E/4=64]
    const float4* __restrict__ layers4,     // [L, B, S, F/4=192]
    const float* __restrict__ layer_weights,// [L]
    const float* __restrict__ gamma,        // [1]
    float4* __restrict__ out4)              // [B, W, (E+F)/4=256]
{
    const int t = threadIdx.x;            // 0..191 -> float4 index within F
    const bool do_emb = (t < 64);

    // Softmax once (fast-path weights fold in gamma/len(=2)).
    const float lw0 = __ldg(layer_weights + 0), lw1 = __ldg(layer_weights + 1);
    const float lw2 = __ldg(layer_weights + 2), lw3 = __ldg(layer_weights + 3);
    const float g   = __ldg(gamma);
    const float mx  = fmaxf(fmaxf(lw0, lw1), fmaxf(lw2, lw3));
    const float e0  = __expf(lw0 - mx), e1 = __expf(lw1 - mx);
    const float e2  = __expf(lw2 - mx), e3 = __expf(lw3 - mx);
    const float sc  = g * 0.5f / (e0 + e1 + e2 + e3);
    const float h0 = e0 * sc, h1 = e1 * sc, h2 = e2 * sc, h3 = e3 * sc;

    int bwA = blockIdx.x;
    if (bwA >= NTOT) return;

    Stage A, B;
    issue_stage(A, bwA, t, do_emb, word_indices, span_starts, span_ends, emb4, layers4);

    int bwB = bwA + NCTA;
    while (true) {
        const bool haveB = (bwB < NTOT);
        if (haveB)
            issue_stage(B, bwB, t, do_emb, word_indices, span_starts, span_ends, emb4, layers4);
        consume_stage(A, t, do_emb, h0, h1, h2, h3,
                      layers4, layer_weights, gamma, out4);
        if (!haveB) return;

        const int bwA2 = bwB + NCTA;
        const bool haveA = (bwA2 < NTOT);
        if (haveA)
            issue_stage(A, bwA2, t, do_emb, word_indices, span_starts, span_ends, emb4, layers4);
        consume_stage(B, t, do_emb, h0, h1, h2, h3,
                      layers4, layer_weights, gamma, out4);
        if (!haveA) return;

        bwB = bwA2 + NCTA;
    }
}

extern "C" void kernel_launch(void* const* d_in, const int* in_sizes, int n_in,
                              void* d_out, int out_size)
{
    const int*    word_indices  = (const int*)   d_in[0];
    const int*    span_starts   = (const int*)   d_in[1];
    const int*    span_ends     = (const int*)   d_in[2];
    const float4* emb4          = (const float4*)d_in[3];
    const float4* layers4       = (const float4*)d_in[4];
    const float*  layer_weights = (const float*) d_in[5];
    const float*  gamma         = (const float*) d_in[6];
    float4*       out4          = (float4*)      d_out;

    (void)in_sizes; (void)n_in; (void)out_size;

    bert_lexer_pipe<<<NCTA, 192>>>(word_indices, span_starts, span_ends,
                                   emb4, layers4, layer_weights, gamma, out4);
}

// round 9
// speedup vs baseline: 1.0880x; 1.0880x over previous
#include <cuda_runtime.h>

// Problem constants (fixed by the reference):
// B=16, W=256, S=512, F=768, L=4, E=256, V=50000
#define BB 16
#define WW 256
#define SS 512
#define NW (WW - 1)

// float4 strides inside layers[L, B, S, F/4=192]
#define LSTRIDE (BB * SS * 192)   // 1,572,864
#define BSTRIDE (SS * 192)        //    98,304

// Streaming load: non-coherent, promote L2 fill granularity to 256B.
__device__ __forceinline__ float4 ldg_stream(const float4* p) {
    float4 v;
    asm("ld.global.nc.L2::256B.v4.f32 {%0,%1,%2,%3}, [%4];"
        : "=f"(v.x), "=f"(v.y), "=f"(v.z), "=f"(v.w)
        : "l"(p));
    return v;
}

// Generic (slow) path: arbitrary span length. Never taken with this dataset
// (all spans are len==2); kept for correctness on arbitrary inputs.
__device__ __noinline__ float4 span_mix_generic(
    const float4* __restrict__ layers4, int b, int ss, int se, int f4,
    float w0, float w1, float w2, float w3, float g)
{
    float4 acc = make_float4(0.f, 0.f, 0.f, 0.f);
    const int len = se - ss;
    if (len <= 0) return acc;
    for (int s = ss; s < se; s++) {
        const float4* p = layers4 + (size_t)b * BSTRIDE + (size_t)s * 192 + f4;
        float4 v0 = p[0 * LSTRIDE];
        float4 v1 = p[1 * LSTRIDE];
        float4 v2 = p[2 * LSTRIDE];
        float4 v3 = p[3 * LSTRIDE];
        acc.x += w0*v0.x + w1*v1.x + w2*v2.x + w3*v3.x;
        acc.y += w0*v0.y + w1*v1.y + w2*v2.y + w3*v3.y;
        acc.z += w0*v0.z + w1*v1.z + w2*v2.z + w3*v3.z;
        acc.w += w0*v0.w + w1*v1.w + w2*v2.w + w3*v3.w;
    }
    const float sc = g / (float)len;
    acc.x *= sc; acc.y *= sc; acc.z *= sc; acc.w *= sc;
    return acc;
}

// Grid: TWO blocks per (b, w) pair = 8192 blocks of 96 threads.
// Block (word, h) owns float4s f4 = h*96 + t of the F=768 bert slice
// (8 front-batched streaming loads per thread). The h==0 block's threads
// 0..63 additionally gather the word's 256-float embedding row.
// Rationale vs the 192-thread version: same structure/instruments, but
// halved CTA lifetime shrinks the final partial wave (4096 CTAs / 760
// slots = 5.39 waves, 39%-full tail) -> less DRAM idle time at the tail.
__global__ __launch_bounds__(96, 12)
void bert_lexer_fused(
    const int* __restrict__ word_indices,   // [B, W]
    const int* __restrict__ span_starts,    // [B, W-1]
    const int* __restrict__ span_ends,      // [B, W-1]
    const float4* __restrict__ emb4,        // [V, E/4=64]
    const float4* __restrict__ layers4,     // [L, B, S, F/4=192]
    const float* __restrict__ layer_weights,// [L]
    const float* __restrict__ gamma,        // [1]
    float4* __restrict__ out4)              // [B, W, (E+F)/4=256]
{
    const int bx   = blockIdx.x;
    const int word = bx >> 1;          // b*W + w
    const int h    = bx & 1;           // which half of the F slice
    const int b    = word >> 8;        // W = 256
    const int w    = word & (WW - 1);
    const int t    = threadIdx.x;      // 0..95
    const int f4   = h * 96 + t;       // float4 index within F (0..191)

    float4* __restrict__ outrow = out4 + (size_t)word * 256;

    // ---- embedding gather chain (h==0 blocks, threads 0..63), first ----
    float4 ev = make_float4(0.f, 0.f, 0.f, 0.f);
    const bool do_emb = (h == 0) && (t < 64);
    if (do_emb) {
        const int idx = __ldg(word_indices + word);
        ev = ldg_stream(emb4 + (size_t)idx * 64 + t);
    }

    // ---- bert slice: softmax-weighted layer mix averaged over the span ----
    float4 acc = make_float4(0.f, 0.f, 0.f, 0.f);
    if (w > 0) {
        const int si  = b * NW + (w - 1);
        const int ss  = __ldg(span_starts + si);
        const int se  = __ldg(span_ends   + si);
        const int len = se - ss;
        if (len > 0) {
            if (len == 2) {
                // Fast path: 8 streaming loads front-batched.
                const float4* base = layers4 + (size_t)b * BSTRIDE + (size_t)ss * 192 + f4;
                float4 a0 = ldg_stream(base + 0 * LSTRIDE      );
                float4 b0 = ldg_stream(base + 0 * LSTRIDE + 192);
                float4 a1 = ldg_stream(base + 1 * LSTRIDE      );
                float4 b1 = ldg_stream(base + 1 * LSTRIDE + 192);
                float4 a2 = ldg_stream(base + 2 * LSTRIDE      );
                float4 b2 = ldg_stream(base + 2 * LSTRIDE + 192);
                float4 a3 = ldg_stream(base + 3 * LSTRIDE      );
                float4 b3 = ldg_stream(base + 3 * LSTRIDE + 192);

                // Per-thread softmax (cached scalar loads, overlap the LDGs).
                float lw0 = __ldg(layer_weights + 0), lw1 = __ldg(layer_weights + 1);
                float lw2 = __ldg(layer_weights + 2), lw3 = __ldg(layer_weights + 3);
                float g   = __ldg(gamma);
                float m  = fmaxf(fmaxf(lw0, lw1), fmaxf(lw2, lw3));
                float e0 = __expf(lw0 - m), e1 = __expf(lw1 - m);
                float e2 = __expf(lw2 - m), e3 = __expf(lw3 - m);
                float sc = g * 0.5f / (e0 + e1 + e2 + e3);
                float w0 = e0 * sc, w1 = e1 * sc, w2 = e2 * sc, w3 = e3 * sc;

                acc.x = w0*(a0.x+b0.x) + w1*(a1.x+b1.x) + w2*(a2.x+b2.x) + w3*(a3.x+b3.x);
                acc.y = w0*(a0.y+b0.y) + w1*(a1.y+b1.y) + w2*(a2.y+b2.y) + w3*(a3.y+b3.y);
                acc.z = w0*(a0.z+b0.z) + w1*(a1.z+b1.z) + w2*(a2.z+b2.z) + w3*(a3.z+b3.z);
                acc.w = w0*(a0.w+b0.w) + w1*(a1.w+b1.w) + w2*(a2.w+b2.w) + w3*(a3.w+b3.w);
            } else {
                float lw0 = __ldg(layer_weights + 0), lw1 = __ldg(layer_weights + 1);
                float lw2 = __ldg(layer_weights + 2), lw3 = __ldg(layer_weights + 3);
                float g   = __ldg(gamma);
                float m  = fmaxf(fmaxf(lw0, lw1), fmaxf(lw2, lw3));
                float e0 = __expf(lw0 - m), e1 = __expf(lw1 - m);
                float e2 = __expf(lw2 - m), e3 = __expf(lw3 - m);
                float inv = 1.0f / (e0 + e1 + e2 + e3);
                acc = span_mix_generic(layers4, b, ss, se, f4,
                                       e0*inv, e1*inv, e2*inv, e3*inv, g);
            }
        }
    }

    // Evict-first streaming stores: output has no reuse, keep L2 for layers.
    if (do_emb) __stcs(outrow + t, ev);
    __stcs(outrow + 64 + f4, acc);   // w==0 or empty span -> zeros (reference)
}

extern "C" void kernel_launch(void* const* d_in, const int* in_sizes, int n_in,
                              void* d_out, int out_size)
{
    const int*    word_indices  = (const int*)   d_in[0];
    const int*    span_starts   = (const int*)   d_in[1];
    const int*    span_ends     = (const int*)   d_in[2];
    const float4* emb4          = (const float4*)d_in[3];
    const float4* layers4       = (const float4*)d_in[4];
    const float*  layer_weights = (const float*) d_in[5];
    const float*  gamma         = (const float*) d_in[6];
    float4*       out4          = (float4*)      d_out;

    (void)in_sizes; (void)n_in; (void)out_size;

    bert_lexer_fused<<<BB * WW * 2, 96>>>(word_indices, span_starts, span_ends,
                                          emb4, layers4, layer_weights, gamma, out4);
}

// round 10
// speedup vs baseline: 1.2095x; 1.1116x over previous
#include <cuda_runtime.h>

// Problem constants (fixed by the reference):
// B=16, W=256, S=512, F=768, L=4, E=256, V=50000
#define BB 16
#define WW 256
#define SS 512
#define LL 4
#define NW (WW - 1)

// float4 strides inside layers[L, B, S, F/4=192]
#define LSTRIDE (BB * SS * 192)   // 1,572,864
#define BSTRIDE (SS * 192)        //    98,304

// Pure streaming load (layers): non-coherent, DO NOT allocate in L1 (zero
// reuse; keeps L1 for embedding rows + store coalescing), 256B L2 fill
// granularity (fewer, larger DRAM bursts; rows are 256B-aligned multiples).
__device__ __forceinline__ float4 ldg_stream_noL1(const float4* p) {
    float4 v;
    asm("ld.global.nc.L1::no_allocate.L2::256B.v4.f32 {%0,%1,%2,%3}, [%4];"
        : "=f"(v.x), "=f"(v.y), "=f"(v.z), "=f"(v.w)
        : "l"(p));
    return v;
}

// Embedding-row load: non-coherent, L1-allocating (duplicate word indices
// give real L1/L2 reuse), 256B L2 fill granularity.
__device__ __forceinline__ float4 ldg_emb(const float4* p) {
    float4 v;
    asm("ld.global.nc.L2::256B.v4.f32 {%0,%1,%2,%3}, [%4];"
        : "=f"(v.x), "=f"(v.y), "=f"(v.z), "=f"(v.w)
        : "l"(p));
    return v;
}

// Grid: one block per (b, w) pair = 4096 blocks, 192 threads.
// Every thread owns one float4 of the F=768 bert slice (8 front-batched
// streaming loads). Threads 0..63 additionally gather one float4 of the
// E=256 embedding row. No smem, no barriers.
__global__ __launch_bounds__(192, 5)
void bert_lexer_fused(
    const int* __restrict__ word_indices,   // [B, W]
    const int* __restrict__ span_starts,    // [B, W-1]
    const int* __restrict__ span_ends,      // [B, W-1]
    const float4* __restrict__ emb4,        // [V, E/4=64]
    const float4* __restrict__ layers4,     // [L, B, S, F/4=192]
    const float* __restrict__ layer_weights,// [L]
    const float* __restrict__ gamma,        // [1]
    float4* __restrict__ out4)              // [B, W, (E+F)/4=256]
{
    const int bw = blockIdx.x;        // b*W + w
    const int b  = bw >> 8;           // W = 256
    const int w  = bw & (WW - 1);
    const int t  = threadIdx.x;       // 0..191 -> float4 index within F

    float4* __restrict__ outrow = out4 + (size_t)bw * 256;

    // ---- embedding gather chain (threads 0..63), issued first ----
    float4 ev = make_float4(0.f, 0.f, 0.f, 0.f);
    const bool do_emb = (t < 64);
    if (do_emb) {
        const int idx = __ldg(word_indices + bw);
        ev = ldg_emb(emb4 + (size_t)idx * 64 + t);
    }

    // ---- bert slice: softmax-weighted layer mix averaged over the span ----
    float4 acc = make_float4(0.f, 0.f, 0.f, 0.f);
    if (w > 0) {
        const int si  = b * NW + (w - 1);
        const int ss  = __ldg(span_starts + si);
        const int se  = __ldg(span_ends   + si);
        const int len = se - ss;
        if (len > 0) {
            if (len == 2) {
                // Fast path (all spans in this dataset): 8 streaming loads
                // front-batched with nothing ahead of them.
                const float4* base = layers4 + (size_t)b * BSTRIDE + (size_t)ss * 192 + t;
                float4 a0 = ldg_stream_noL1(base + 0 * LSTRIDE      );
                float4 b0 = ldg_stream_noL1(base + 0 * LSTRIDE + 192);
                float4 a1 = ldg_stream_noL1(base + 1 * LSTRIDE      );
                float4 b1 = ldg_stream_noL1(base + 1 * LSTRIDE + 192);
                float4 a2 = ldg_stream_noL1(base + 2 * LSTRIDE      );
                float4 b2 = ldg_stream_noL1(base + 2 * LSTRIDE + 192);
                float4 a3 = ldg_stream_noL1(base + 3 * LSTRIDE      );
                float4 b3 = ldg_stream_noL1(base + 3 * LSTRIDE + 192);

                // Per-thread softmax (cached scalar loads, overlap the LDGs).
                float lw0 = __ldg(layer_weights + 0), lw1 = __ldg(layer_weights + 1);
                float lw2 = __ldg(layer_weights + 2), lw3 = __ldg(layer_weights + 3);
                float g   = __ldg(gamma);
                float m  = fmaxf(fmaxf(lw0, lw1), fmaxf(lw2, lw3));
                float e0 = __expf(lw0 - m), e1 = __expf(lw1 - m);
                float e2 = __expf(lw2 - m), e3 = __expf(lw3 - m);
                float sc = g * 0.5f / (e0 + e1 + e2 + e3);
                float w0 = e0 * sc, w1 = e1 * sc, w2 = e2 * sc, w3 = e3 * sc;

                acc.x = w0*(a0.x+b0.x) + w1*(a1.x+b1.x) + w2*(a2.x+b2.x) + w3*(a3.x+b3.x);
                acc.y = w0*(a0.y+b0.y) + w1*(a1.y+b1.y) + w2*(a2.y+b2.y) + w3*(a3.y+b3.y);
                acc.z = w0*(a0.z+b0.z) + w1*(a1.z+b1.z) + w2*(a2.z+b2.z) + w3*(a3.z+b3.z);
                acc.w = w0*(a0.w+b0.w) + w1*(a1.w+b1.w) + w2*(a2.w+b2.w) + w3*(a3.w+b3.w);
            } else {
                // Generic path (not hit with this dataset, kept for correctness).
                float lw0 = __ldg(layer_weights + 0), lw1 = __ldg(layer_weights + 1);
                float lw2 = __ldg(layer_weights + 2), lw3 = __ldg(layer_weights + 3);
                float g   = __ldg(gamma);
                float m  = fmaxf(fmaxf(lw0, lw1), fmaxf(lw2, lw3));
                float e0 = __expf(lw0 - m), e1 = __expf(lw1 - m);
                float e2 = __expf(lw2 - m), e3 = __expf(lw3 - m);
                float inv = 1.0f / (e0 + e1 + e2 + e3);
                float swt[LL] = {e0 * inv, e1 * inv, e2 * inv, e3 * inv};
                for (int s = ss; s < se; s++) {
                    #pragma unroll
                    for (int l = 0; l < LL; l++) {
                        float4 v = layers4[(size_t)l * LSTRIDE + (size_t)b * BSTRIDE
                                           + (size_t)s * 192 + t];
                        float wl = swt[l];
                        acc.x += wl * v.x; acc.y += wl * v.y;
                        acc.z += wl * v.z; acc.w += wl * v.w;
                    }
                }
                const float sc = g / (float)len;
                acc.x *= sc; acc.y *= sc; acc.z *= sc; acc.w *= sc;
            }
        }
    }

    // Evict-first streaming stores: output has no reuse, keep L2 for layers.
    if (do_emb) __stcs(outrow + t, ev);
    __stcs(outrow + 64 + t, acc);   // w==0 or empty span -> zeros (reference)
}

extern "C" void kernel_launch(void* const* d_in, const int* in_sizes, int n_in,
                              void* d_out, int out_size)
{
    const int*    word_indices  = (const int*)   d_in[0];
    const int*    span_starts   = (const int*)   d_in[1];
    const int*    span_ends     = (const int*)   d_in[2];
    const float4* emb4          = (const float4*)d_in[3];
    const float4* layers4       = (const float4*)d_in[4];
    const float*  layer_weights = (const float*) d_in[5];
    const float*  gamma         = (const float*) d_in[6];
    float4*       out4          = (float4*)      d_out;

    (void)in_sizes; (void)n_in; (void)out_size;

    bert_lexer_fused<<<BB * WW, 192>>>(word_indices, span_starts, span_ends,
                                       emb4, layers4, layer_weights, gamma, out4);
}